// round 7
// baseline (speedup 1.0000x reference)
#include <cuda_runtime.h>
#include <cuda_fp16.h>
#include <cuda_pipeline.h>
#include <mma.h>
#include <math.h>
#include <cstdint>

using namespace nvcuda;

// ---------------- problem constants ----------------
#define NTOK   65536
#define BATCH  8
#define SEQ    8192
#define DMODEL 512
#define NHEAD  8
#define NKV    2
#define DHEAD  64
#define MFEAT  64
#define DFF    2048
#define NCLS   2
#define EPSV   1e-6f

// ---------------- scratch ----------------
__device__ float  g_x   [NTOK * DMODEL];
__device__ __half g_h   [NTOK * DMODEL];
__device__ __half g_qkv [NTOK * (DMODEL + 2*128)];   // q | k | v contiguous blocks
__device__ __half g_pqk [NTOK * (NHEAD + NKV) * MFEAT];  // pq rows then pk rows
__device__ __half g_att [NTOK * DMODEL];
__device__ __half g_gu  [NTOK * DFF];
__device__ float  g_kvp [128 * 64 * 65];
__device__ float  g_xm  [BATCH * DMODEL];
// converted fp16 weights, row-major [K, N]
__device__ __half g_WqkvH[DMODEL * 768];
__device__ __half g_WphiH[DHEAD * MFEAT];
__device__ __half g_WoH  [DMODEL * DMODEL];
__device__ __half g_WguH [DMODEL * (2*DFF)];   // interleaved g,u columns
__device__ __half g_WdH  [DFF * DMODEL];

struct alignas(8) half4 { __half2 a, b; };
__device__ __forceinline__ half4 f4_to_h4(float4 v) {
    half4 r; r.a = __floats2half2_rn(v.x, v.y); r.b = __floats2half2_rn(v.z, v.w); return r;
}

// ---------------- single merged weight conversion ----------------
#define CQKV 393216      // 512*768
#define CGU  2097152     // 512*4096
#define CPHI 4096
#define CWO  262144
#define CWD  1048576
#define CTOT (CQKV + CGU + CPHI + CWO + CWD)   // 3805184

__global__ void conv_all(const float* __restrict__ Wq, const float* __restrict__ Wk,
                         const float* __restrict__ Wv, const float* __restrict__ Wg,
                         const float* __restrict__ Wu, const float* __restrict__ Wphi,
                         const float* __restrict__ Wo, const float* __restrict__ Wd,
                         __half* __restrict__ WqkvH, __half* __restrict__ WguH,
                         __half* __restrict__ WphiH, __half* __restrict__ WoH,
                         __half* __restrict__ WdH)
{
    int idx = blockIdx.x * 256 + threadIdx.x;
    if (idx < CQKV) {
        int r = idx / 768, c = idx % 768;
        float v = (c < 512) ? Wq[r * 512 + c]
                            : (c < 640 ? Wk[r * 128 + c - 512] : Wv[r * 128 + c - 640]);
        WqkvH[idx] = __float2half(v);
        return;
    }
    idx -= CQKV;
    if (idx < CGU) {
        int r = idx >> 12, c = idx & 4095;
        int j = c >> 1;
        float v = (c & 1) ? Wu[r * DFF + j] : Wg[r * DFF + j];
        WguH[idx] = __float2half(v);
        return;
    }
    idx -= CGU;
    if (idx < CPHI) { WphiH[idx] = __float2half(Wphi[idx]); return; }
    idx -= CPHI;
    if (idx < CWO)  { WoH[idx]   = __float2half(Wo[idx]);   return; }
    idx -= CWO;
    if (idx < CWD)  { WdH[idx]   = __float2half(Wd[idx]);   return; }
}

// ---------------- fp16 multi-stage WMMA GEMM ----------------
// C[M,Nc] = A[M,K] @ B[K,Nc]; BM=128, BK=32, 4 stages.
// Grid: x = n-tile (A-sharing blocks adjacent -> L2 reuse), y = m-tile.
#define EPI_QKV    0
#define EPI_EXPABS 1
#define EPI_RES    2
#define EPI_SWIGLU 3
#define STAGES 4

template<int BN, int EPI>
__global__ __launch_bounds__(256, 2) void gemm_h(
    const __half* __restrict__ A, const __half* __restrict__ B,
    void* __restrict__ Cout, const float* __restrict__ X,
    int M, int K, int Nc)
{
    constexpr int BM = 128, BK = 32;
    constexpr int LDA_S = BK + 8;
    constexpr int LDB_S = BN + 8;
    constexpr int LDC_S = BN + 4;
    constexpr int NF = BN / 32;
    constexpr int A_ELE = BM * LDA_S;
    constexpr int B_ELE = BK * LDB_S;
    constexpr int STG_ELE = A_ELE + B_ELE;

    extern __shared__ __align__(16) char smem_raw[];
    __half* stg = (__half*)smem_raw;

    const int tid  = threadIdx.x;
    const int bm   = blockIdx.y * BM;     // m-tile on y (slow axis)
    const int bn   = blockIdx.x * BN;     // n-tile on x (fast axis -> A L2 reuse)
    const int warp = tid >> 5;
    const int wm   = (warp >> 1) * 32;
    const int wn   = (warp & 1) * (BN / 2);

    wmma::fragment<wmma::accumulator, 16, 16, 16, float> c[2][NF];
#pragma unroll
    for (int i = 0; i < 2; i++)
#pragma unroll
        for (int j = 0; j < NF; j++) wmma::fill_fragment(c[i][j], 0.0f);

    const int nK = K / BK;

    auto load_stage = [&](int kt, int s) {
        __half* As = stg + s * STG_ELE;
        __half* Bs = As + A_ELE;
#pragma unroll
        for (int i = 0; i < 2; i++) {
            int idx = tid + i * 256;
            int r  = idx >> 2;
            int cc = (idx & 3) * 8;
            __pipeline_memcpy_async(&As[r * LDA_S + cc],
                                    &A[(size_t)(bm + r) * K + kt + cc], 16);
        }
        constexpr int CH = BN / 8;
        constexpr int NB = (BK * CH) / 256;
#pragma unroll
        for (int i = 0; i < NB; i++) {
            int idx = tid + i * 256;
            int r  = idx / CH;
            int cc = (idx % CH) * 8;
            __pipeline_memcpy_async(&Bs[r * LDB_S + cc],
                                    &B[(size_t)(kt + r) * Nc + bn + cc], 16);
        }
    };

#pragma unroll
    for (int s = 0; s < STAGES - 1; s++) {
        if (s < nK) load_stage(s * BK, s);
        __pipeline_commit();
    }

    for (int kt_i = 0; kt_i < nK; kt_i++) {
        __pipeline_wait_prior(STAGES - 2);
        __syncthreads();
        int ldk = kt_i + STAGES - 1;
        if (ldk < nK) load_stage(ldk * BK, ldk % STAGES);
        __pipeline_commit();

        int s = kt_i % STAGES;
        __half* As = stg + s * STG_ELE;
        __half* Bs = As + A_ELE;
#pragma unroll
        for (int kk = 0; kk < BK; kk += 16) {
            wmma::fragment<wmma::matrix_a, 16, 16, 16, __half, wmma::row_major> a[2];
            wmma::fragment<wmma::matrix_b, 16, 16, 16, __half, wmma::row_major> b[NF];
#pragma unroll
            for (int i = 0; i < 2; i++)
                wmma::load_matrix_sync(a[i], &As[(wm + i * 16) * LDA_S + kk], LDA_S);
#pragma unroll
            for (int j = 0; j < NF; j++)
                wmma::load_matrix_sync(b[j], &Bs[kk * LDB_S + wn + j * 16], LDB_S);
#pragma unroll
            for (int i = 0; i < 2; i++)
#pragma unroll
                for (int j = 0; j < NF; j++)
                    wmma::mma_sync(c[i][j], a[i], b[j], c[i][j]);
        }
    }

    // epilogue in two 64-row halves through a small smem buffer
    float* Cs = (float*)smem_raw;
    constexpr int F4R = BN / 4;
    constexpr int NIT = (64 * F4R) / 256;
#pragma unroll
    for (int hrow = 0; hrow < 2; hrow++) {
        __syncthreads();
        if ((wm >> 6) == hrow) {
#pragma unroll
            for (int i = 0; i < 2; i++)
#pragma unroll
                for (int j = 0; j < NF; j++)
                    wmma::store_matrix_sync(&Cs[((wm & 63) + i * 16) * LDC_S + wn + j * 16],
                                            c[i][j], LDC_S, wmma::mem_row_major);
        }
        __syncthreads();
#pragma unroll
        for (int i = 0; i < NIT; i++) {
            int e  = tid + i * 256;
            int r  = e / F4R;
            int cc = (e % F4R) * 4;
            float4 vv = *(float4*)&Cs[r * LDC_S + cc];
            int grow = bm + hrow * 64 + r;
            if (EPI == EPI_QKV) {
                __half* dst; int ld, c0;
                if (bn < 512)      { dst = (__half*)Cout;                    ld = 512; c0 = bn; }
                else if (bn < 640) { dst = (__half*)Cout + (size_t)M * 512;  ld = 128; c0 = bn - 512; }
                else               { dst = (__half*)Cout + (size_t)M * 640;  ld = 128; c0 = bn - 640; }
                *(half4*)&dst[(size_t)grow * ld + c0 + cc] = f4_to_h4(vv);
            } else if (EPI == EPI_EXPABS) {
                vv.x = expf(-fabsf(vv.x)); vv.y = expf(-fabsf(vv.y));
                vv.z = expf(-fabsf(vv.z)); vv.w = expf(-fabsf(vv.w));
                *(half4*)&((__half*)Cout)[(size_t)grow * Nc + bn + cc] = f4_to_h4(vv);
            } else if (EPI == EPI_RES) {
                size_t gidx = (size_t)grow * Nc + bn + cc;
                float4 xv = *(const float4*)&X[gidx];
                vv.x += xv.x; vv.y += xv.y; vv.z += xv.z; vv.w += xv.w;
                *(float4*)&((float*)Cout)[gidx] = vv;
            } else { // EPI_SWIGLU
                float s0 = vv.x / (1.0f + expf(-vv.x)) * vv.y;
                float s1 = vv.z / (1.0f + expf(-vv.z)) * vv.w;
                int jo = (bn + cc) >> 1;
                *(__half2*)&((__half*)Cout)[(size_t)grow * (Nc >> 1) + jo] =
                    __floats2half2_rn(s0, s1);
            }
        }
    }
}

// ---------------- gather + rmsnorm ----------------
__global__ __launch_bounds__(128) void gather_rmsnorm_kernel(
    const int* __restrict__ ids, const float* __restrict__ emb,
    const float* __restrict__ xin, const float* __restrict__ g,
    float* __restrict__ xout, __half* __restrict__ h)
{
    int token = blockIdx.x;
    const float* src = ids ? (emb + (size_t)ids[token] * DMODEL)
                           : (xin + (size_t)token * DMODEL);
    int c = threadIdx.x * 4;
    float4 v = *(const float4*)&src[c];
    float ss = v.x * v.x + v.y * v.y + v.z * v.z + v.w * v.w;
#pragma unroll
    for (int off = 16; off > 0; off >>= 1) ss += __shfl_xor_sync(0xffffffffu, ss, off);
    __shared__ float sred[4];
    int warp = threadIdx.x >> 5, lane = threadIdx.x & 31;
    if (lane == 0) sred[warp] = ss;
    __syncthreads();
    float tot = sred[0] + sred[1] + sred[2] + sred[3];
    float scale = rsqrtf(tot * (1.0f / DMODEL) + EPSV);
    float4 gv = *(const float4*)&g[c];
    float4 o;
    o.x = v.x * scale * gv.x; o.y = v.y * scale * gv.y;
    o.z = v.z * scale * gv.z; o.w = v.w * scale * gv.w;
    if (xout) *(float4*)&xout[(size_t)token * DMODEL + c] = v;
    *(half4*)&h[(size_t)token * DMODEL + c] = f4_to_h4(o);
}

// ---------------- kv state partials (16-token tiles) ----------------
__global__ __launch_bounds__(256) void kv_partial_kernel(
    const __half* __restrict__ pk, const __half* __restrict__ v, float* __restrict__ kvp)
{
    int pair = blockIdx.x, chunk = blockIdx.y;
    int b = pair >> 1, kh = pair & 1;
    int tid = threadIdx.x;
    int ti = tid >> 4, tj = tid & 15;
    float acc[4][4], zacc[4];
#pragma unroll
    for (int a = 0; a < 4; a++) { zacc[a] = 0.f;
#pragma unroll
        for (int bb = 0; bb < 4; bb++) acc[a][bb] = 0.f; }
    __shared__ float spk[16][64], sv[16][64];
    int s0 = chunk * 1024;
    for (int sb = 0; sb < 1024; sb += 16) {
#pragma unroll
        for (int j = 0; j < 4; j++) {
            int idx = tid + j * 256;
            int t = idx >> 6, lane = idx & 63;
            int token = b * SEQ + s0 + sb + t;
            size_t base = ((size_t)token * NKV + kh) * 64 + lane;
            spk[t][lane] = __half2float(pk[base]);
            sv[t][lane]  = __half2float(v[base]);
        }
        __syncthreads();
#pragma unroll
        for (int t = 0; t < 16; t++) {
            float pm[4], vd[4];
#pragma unroll
            for (int mm = 0; mm < 4; mm++) pm[mm] = spk[t][ti * 4 + mm];
#pragma unroll
            for (int dd = 0; dd < 4; dd++) vd[dd] = sv[t][tj * 4 + dd];
#pragma unroll
            for (int mm = 0; mm < 4; mm++) {
#pragma unroll
                for (int dd = 0; dd < 4; dd++) acc[mm][dd] = fmaf(pm[mm], vd[dd], acc[mm][dd]);
                if (tj == 0) zacc[mm] += pm[mm];
            }
        }
        __syncthreads();
    }
    int pc = pair * 8 + chunk;
#pragma unroll
    for (int mm = 0; mm < 4; mm++) {
#pragma unroll
        for (int dd = 0; dd < 4; dd++)
            kvp[(size_t)pc * 4160 + (ti * 4 + mm) * 65 + tj * 4 + dd] = acc[mm][dd];
        if (tj == 0) kvp[(size_t)pc * 4160 + (ti * 4 + mm) * 65 + 64] = zacc[mm];
    }
}

// ---------------- num/den with fused chunk reduction ----------------
__global__ __launch_bounds__(256) void numden_kernel(
    const __half* __restrict__ pq, const float* __restrict__ kvp, __half* __restrict__ att)
{
    int b = blockIdx.y;
    __shared__ float skv[2 * 64 * 65];
    __shared__ float spq[4][64];
    // reduce the 8 per-chunk partials while staging into smem (kvp is L2-resident)
    for (int idx = threadIdx.x; idx < 8320; idx += 256) {
        int kh = idx / 4160, off = idx % 4160;
        const float* src = kvp + (size_t)((b * 2 + kh) * 8) * 4160 + off;
        float s = 0.f;
#pragma unroll
        for (int c = 0; c < 8; c++) s += src[c * 4160];
        skv[idx] = s;
    }
    __syncthreads();
    int group = threadIdx.x >> 6, lane = threadIdx.x & 63;
    int base = blockIdx.x * 128;
    for (int it = 0; it < 32; it++) {
        int th = base + it * 4 + group;
        size_t row = ((size_t)b * (SEQ * NHEAD) + th) * 64;
        spq[group][lane] = __half2float(pq[row + lane]);
        __syncthreads();
        int h = th & 7;
        const float* kvh = &skv[(h >> 2) * 4160];
        float num = 0.f, den = 0.f;
#pragma unroll
        for (int m = 0; m < 64; m++) {
            float p = spq[group][m];
            num = fmaf(p, kvh[m * 65 + lane], num);
            den = fmaf(p, kvh[m * 65 + 64], den);
        }
        att[row + lane] = __float2half(num / (den + EPSV));
        __syncthreads();
    }
}

// ---------------- pool + head ----------------
__global__ __launch_bounds__(256) void pool_kernel(
    const float* __restrict__ x, float* __restrict__ xm)
{
    int b = blockIdx.y;
    int c = blockIdx.x * 64 + (threadIdx.x & 63);
    int part = threadIdx.x >> 6;
    float s = 0.f;
    for (int t = part; t < SEQ; t += 4)
        s += x[((size_t)b * SEQ + t) * DMODEL + c];
    __shared__ float red[4][64];
    red[part][threadIdx.x & 63] = s;
    __syncthreads();
    if (part == 0) {
        int l = threadIdx.x & 63;
        xm[b * DMODEL + c] = red[0][l] + red[1][l] + red[2][l] + red[3][l];
    }
}

__global__ __launch_bounds__(512) void head_kernel(
    const float* __restrict__ xm, const float* __restrict__ Wc,
    const float* __restrict__ bc, float* __restrict__ out)
{
    int warp = threadIdx.x >> 5, lane = threadIdx.x & 31;
    int b = warp >> 1, cls = warp & 1;
    float s = 0.f;
    for (int d = lane; d < DMODEL; d += 32)
        s += xm[b * DMODEL + d] * Wc[d * NCLS + cls];
#pragma unroll
    for (int off = 16; off > 0; off >>= 1) s += __shfl_xor_sync(0xffffffffu, s, off);
    if (lane == 0) out[b * NCLS + cls] = s * (1.0f / SEQ) + bc[cls];
}

// ---------------- launch ----------------
#define STG128  (128 * 40 + 32 * 136)
#define STG64   (128 * 40 + 32 * 72)
#define SMEM_BN128_V ((STAGES * STG128) * 2)
#define SMEM_BN64_V  ((STAGES * STG64) * 2)

extern "C" void kernel_launch(void* const* d_in, const int* in_sizes, int n_in,
                              void* d_out, int out_size)
{
    (void)in_sizes; (void)n_in; (void)out_size;
    const int*   ids  = (const int*)  d_in[0];
    const float* emb  = (const float*)d_in[1];
    const float* Wq   = (const float*)d_in[2];
    const float* Wk   = (const float*)d_in[3];
    const float* Wv   = (const float*)d_in[4];
    const float* Wphi = (const float*)d_in[5];
    const float* Wo   = (const float*)d_in[6];
    const float* g1   = (const float*)d_in[7];
    const float* g2   = (const float*)d_in[8];
    const float* Wg   = (const float*)d_in[9];
    const float* Wu   = (const float*)d_in[10];
    const float* Wd   = (const float*)d_in[11];
    const float* Wc   = (const float*)d_in[12];
    const float* bc   = (const float*)d_in[13];
    float* out = (float*)d_out;

    float *x, *kvp, *xm;
    __half *h, *qkv, *pqk, *att, *gu;
    __half *WqkvH, *WphiH, *WoH, *WguH, *WdH;
    cudaGetSymbolAddress((void**)&x,    g_x);
    cudaGetSymbolAddress((void**)&h,    g_h);
    cudaGetSymbolAddress((void**)&qkv,  g_qkv);
    cudaGetSymbolAddress((void**)&pqk,  g_pqk);
    cudaGetSymbolAddress((void**)&att,  g_att);
    cudaGetSymbolAddress((void**)&gu,   g_gu);
    cudaGetSymbolAddress((void**)&kvp,  g_kvp);
    cudaGetSymbolAddress((void**)&xm,   g_xm);
    cudaGetSymbolAddress((void**)&WqkvH, g_WqkvH);
    cudaGetSymbolAddress((void**)&WphiH, g_WphiH);
    cudaGetSymbolAddress((void**)&WoH,   g_WoH);
    cudaGetSymbolAddress((void**)&WguH,  g_WguH);
    cudaGetSymbolAddress((void**)&WdH,   g_WdH);

    cudaFuncSetAttribute(gemm_h<128, EPI_QKV>,    cudaFuncAttributeMaxDynamicSharedMemorySize, SMEM_BN128_V);
    cudaFuncSetAttribute(gemm_h<128, EPI_RES>,    cudaFuncAttributeMaxDynamicSharedMemorySize, SMEM_BN128_V);
    cudaFuncSetAttribute(gemm_h<128, EPI_SWIGLU>, cudaFuncAttributeMaxDynamicSharedMemorySize, SMEM_BN128_V);
    cudaFuncSetAttribute(gemm_h<64,  EPI_EXPABS>, cudaFuncAttributeMaxDynamicSharedMemorySize, SMEM_BN64_V);

    // 1. merged weight conversion (one launch)
    conv_all<<<(CTOT + 255) / 256, 256>>>(Wq, Wk, Wv, Wg, Wu, Wphi, Wo, Wd,
                                          WqkvH, WguH, WphiH, WoH, WdH);

    // 2. embedding gather + rmsnorm
    gather_rmsnorm_kernel<<<NTOK, 128>>>(ids, emb, nullptr, g1, x, h);

    // 3. fused qkv projection (grid: x=n, y=m)
    {
        dim3 grid(768 / 128, NTOK / 128);
        gemm_h<128, EPI_QKV><<<grid, 256, SMEM_BN128_V>>>(h, WqkvH, qkv, nullptr, NTOK, DMODEL, 768);
    }

    // 4. single Laplacian feature-map GEMM over q-rows + k-rows (contiguous)
    {
        dim3 grid(1, NTOK * (NHEAD + NKV) / 128);   // M = 655360
        gemm_h<64, EPI_EXPABS><<<grid, 256, SMEM_BN64_V>>>(
            qkv, WphiH, pqk, nullptr, NTOK * (NHEAD + NKV), DHEAD, MFEAT);
    }

    // 5. global kv state partials
    {
        dim3 gp(BATCH * NKV, 8);
        kv_partial_kernel<<<gp, 256>>>(pqk + (size_t)NTOK * NHEAD * MFEAT,
                                       qkv + (size_t)NTOK * 640, kvp);
    }

    // 6. num/den (fused kv-chunk reduction) -> attn   [this is the profiled launch]
    {
        dim3 gn(SEQ * NHEAD / 128, BATCH);
        numden_kernel<<<gn, 256>>>(pqk, kvp, att);
    }

    // 7. output projection + residual
    {
        dim3 grid(DMODEL / 128, NTOK / 128);
        gemm_h<128, EPI_RES><<<grid, 256, SMEM_BN128_V>>>(att, WoH, x, x, NTOK, DMODEL, DMODEL);
    }

    // 8. pre-FFN rmsnorm
    gather_rmsnorm_kernel<<<NTOK, 128>>>(nullptr, nullptr, x, g2, nullptr, h);

    // 9. fused SwiGLU up
    {
        dim3 grid(4096 / 128, NTOK / 128);
        gemm_h<128, EPI_SWIGLU><<<grid, 256, SMEM_BN128_V>>>(h, WguH, gu, nullptr, NTOK, DMODEL, 4096);
    }
    // 10. down proj + residual
    {
        dim3 grid(DMODEL / 128, NTOK / 128);
        gemm_h<128, EPI_RES><<<grid, 256, SMEM_BN128_V>>>(gu, WdH, x, x, NTOK, DFF, DMODEL);
    }

    // 11. mean pool + head
    {
        dim3 gpool(DMODEL / 64, BATCH);
        pool_kernel<<<gpool, 256>>>(x, xm);
    }
    head_kernel<<<1, 512>>>(xm, Wc, bc, out);
}

// round 8
// speedup vs baseline: 1.0026x; 1.0026x over previous
#include <cuda_runtime.h>
#include <cuda_fp16.h>
#include <cuda_pipeline.h>
#include <mma.h>
#include <math.h>
#include <cstdint>

using namespace nvcuda;

// ---------------- problem constants ----------------
#define NTOK   65536
#define BATCH  8
#define SEQ    8192
#define DMODEL 512
#define NHEAD  8
#define NKV    2
#define DHEAD  64
#define MFEAT  64
#define DFF    2048
#define NCLS   2
#define EPSV   1e-6f

// ---------------- scratch ----------------
__device__ float  g_x   [NTOK * DMODEL];
__device__ __half g_h   [NTOK * DMODEL];
__device__ __half g_qkv [NTOK * (DMODEL + 2*128)];   // q | k | v contiguous blocks
__device__ __half g_pqk [NTOK * (NHEAD + NKV) * MFEAT];  // pq rows then pk rows
__device__ __half g_att [NTOK * DMODEL];
__device__ __half g_gu  [NTOK * DFF];
__device__ float  g_kvp [128 * 64 * 65];
__device__ float  g_xm  [BATCH * DMODEL];
// converted fp16 weights, row-major [K, N]
__device__ __half g_WqkvH[DMODEL * 768];
__device__ __half g_WphiH[DHEAD * MFEAT];
__device__ __half g_WoH  [DMODEL * DMODEL];
__device__ __half g_WguH [DMODEL * (2*DFF)];   // interleaved g,u columns
__device__ __half g_WdH  [DFF * DMODEL];

struct alignas(8) half4 { __half2 a, b; };
__device__ __forceinline__ half4 f4_to_h4(float4 v) {
    half4 r; r.a = __floats2half2_rn(v.x, v.y); r.b = __floats2half2_rn(v.z, v.w); return r;
}

// ---------------- single merged weight conversion ----------------
#define CQKV 393216      // 512*768
#define CGU  2097152     // 512*4096
#define CPHI 4096
#define CWO  262144
#define CWD  1048576
#define CTOT (CQKV + CGU + CPHI + CWO + CWD)

__global__ void conv_all(const float* __restrict__ Wq, const float* __restrict__ Wk,
                         const float* __restrict__ Wv, const float* __restrict__ Wg,
                         const float* __restrict__ Wu, const float* __restrict__ Wphi,
                         const float* __restrict__ Wo, const float* __restrict__ Wd,
                         __half* __restrict__ WqkvH, __half* __restrict__ WguH,
                         __half* __restrict__ WphiH, __half* __restrict__ WoH,
                         __half* __restrict__ WdH)
{
    int idx = blockIdx.x * 256 + threadIdx.x;
    if (idx < CQKV) {
        int r = idx / 768, c = idx % 768;
        float v = (c < 512) ? Wq[r * 512 + c]
                            : (c < 640 ? Wk[r * 128 + c - 512] : Wv[r * 128 + c - 640]);
        WqkvH[idx] = __float2half(v);
        return;
    }
    idx -= CQKV;
    if (idx < CGU) {
        int r = idx >> 12, c = idx & 4095;
        int j = c >> 1;
        float v = (c & 1) ? Wu[r * DFF + j] : Wg[r * DFF + j];
        WguH[idx] = __float2half(v);
        return;
    }
    idx -= CGU;
    if (idx < CPHI) { WphiH[idx] = __float2half(Wphi[idx]); return; }
    idx -= CPHI;
    if (idx < CWO)  { WoH[idx]   = __float2half(Wo[idx]);   return; }
    idx -= CWO;
    if (idx < CWD)  { WdH[idx]   = __float2half(Wd[idx]);   return; }
}

// ---------------- fp16 WMMA GEMM: 128 threads, 64x64 warp tile ----------------
// C[M,Nc] = A[M,K] @ B[K,Nc]; BM=128, BK=32, 4 stages, 4 warps (2m x 2n).
#define EPI_QKV    0
#define EPI_EXPABS 1
#define EPI_RES    2
#define EPI_SWIGLU 3
#define STAGES 4
#define NTHR   128

template<int BN, int EPI>
__global__ __launch_bounds__(NTHR, 2) void gemm_h(
    const __half* __restrict__ A, const __half* __restrict__ B,
    void* __restrict__ Cout, const float* __restrict__ X,
    int M, int K, int Nc)
{
    constexpr int BM = 128, BK = 32;
    constexpr int LDA_S = BK + 8;
    constexpr int LDB_S = BN + 8;
    constexpr int LDC_S = BN + 4;
    constexpr int MI = 4;               // 64/16 m-frags per warp
    constexpr int NJ = BN / 32;         // (BN/2)/16 n-frags per warp
    constexpr int A_ELE = BM * LDA_S;
    constexpr int B_ELE = BK * LDB_S;
    constexpr int STG_ELE = A_ELE + B_ELE;

    extern __shared__ __align__(16) char smem_raw[];
    __half* stg = (__half*)smem_raw;

    const int tid  = threadIdx.x;
    const int bm   = blockIdx.y * BM;
    const int bn   = blockIdx.x * BN;
    const int warp = tid >> 5;
    const int wm   = (warp & 1) * 64;          // warp m-offset
    const int wn   = (warp >> 1) * (BN / 2);   // warp n-offset

    wmma::fragment<wmma::accumulator, 16, 16, 16, float> c[MI][NJ];
#pragma unroll
    for (int i = 0; i < MI; i++)
#pragma unroll
        for (int j = 0; j < NJ; j++) wmma::fill_fragment(c[i][j], 0.0f);

    const int nK = K / BK;

    auto load_stage = [&](int kt, int s) {
        __half* As = stg + s * STG_ELE;
        __half* Bs = As + A_ELE;
        // A tile: 128x32 halves = 512 16B-chunks, 4 per thread
#pragma unroll
        for (int i = 0; i < 4; i++) {
            int idx = tid + i * NTHR;
            int r  = idx >> 2;
            int cc = (idx & 3) * 8;
            __pipeline_memcpy_async(&As[r * LDA_S + cc],
                                    &A[(size_t)(bm + r) * K + kt + cc], 16);
        }
        constexpr int CH = BN / 8;
        constexpr int NB = (BK * CH) / NTHR;
#pragma unroll
        for (int i = 0; i < NB; i++) {
            int idx = tid + i * NTHR;
            int r  = idx / CH;
            int cc = (idx % CH) * 8;
            __pipeline_memcpy_async(&Bs[r * LDB_S + cc],
                                    &B[(size_t)(kt + r) * Nc + bn + cc], 16);
        }
    };

#pragma unroll
    for (int s = 0; s < STAGES - 1; s++) {
        if (s < nK) load_stage(s * BK, s);
        __pipeline_commit();
    }

    for (int kt_i = 0; kt_i < nK; kt_i++) {
        __pipeline_wait_prior(STAGES - 2);
        __syncthreads();
        int ldk = kt_i + STAGES - 1;
        if (ldk < nK) load_stage(ldk * BK, ldk % STAGES);
        __pipeline_commit();

        int s = kt_i % STAGES;
        __half* As = stg + s * STG_ELE;
        __half* Bs = As + A_ELE;
#pragma unroll
        for (int kk = 0; kk < BK; kk += 16) {
            wmma::fragment<wmma::matrix_a, 16, 16, 16, __half, wmma::row_major> a[MI];
            wmma::fragment<wmma::matrix_b, 16, 16, 16, __half, wmma::row_major> b[NJ];
#pragma unroll
            for (int i = 0; i < MI; i++)
                wmma::load_matrix_sync(a[i], &As[(wm + i * 16) * LDA_S + kk], LDA_S);
#pragma unroll
            for (int j = 0; j < NJ; j++)
                wmma::load_matrix_sync(b[j], &Bs[kk * LDB_S + wn + j * 16], LDB_S);
#pragma unroll
            for (int i = 0; i < MI; i++)
#pragma unroll
                for (int j = 0; j < NJ; j++)
                    wmma::mma_sync(c[i][j], a[i], b[j], c[i][j]);
        }
    }

    // single-pass epilogue: full 128xBN C through smem
    __syncthreads();
    float* Cs = (float*)smem_raw;                  // 128 * LDC_S floats
#pragma unroll
    for (int i = 0; i < MI; i++)
#pragma unroll
        for (int j = 0; j < NJ; j++)
            wmma::store_matrix_sync(&Cs[(wm + i * 16) * LDC_S + wn + j * 16],
                                    c[i][j], LDC_S, wmma::mem_row_major);
    __syncthreads();

    constexpr int F4R = BN / 4;
    constexpr int NIT = (BM * F4R) / NTHR;
#pragma unroll
    for (int i = 0; i < NIT; i++) {
        int e  = tid + i * NTHR;
        int r  = e / F4R;
        int cc = (e % F4R) * 4;
        float4 vv = *(float4*)&Cs[r * LDC_S + cc];
        int grow = bm + r;
        if (EPI == EPI_QKV) {
            __half* dst; int ld, c0;
            if (bn < 512)      { dst = (__half*)Cout;                    ld = 512; c0 = bn; }
            else if (bn < 640) { dst = (__half*)Cout + (size_t)M * 512;  ld = 128; c0 = bn - 512; }
            else               { dst = (__half*)Cout + (size_t)M * 640;  ld = 128; c0 = bn - 640; }
            *(half4*)&dst[(size_t)grow * ld + c0 + cc] = f4_to_h4(vv);
        } else if (EPI == EPI_EXPABS) {
            vv.x = expf(-fabsf(vv.x)); vv.y = expf(-fabsf(vv.y));
            vv.z = expf(-fabsf(vv.z)); vv.w = expf(-fabsf(vv.w));
            *(half4*)&((__half*)Cout)[(size_t)grow * Nc + bn + cc] = f4_to_h4(vv);
        } else if (EPI == EPI_RES) {
            size_t gidx = (size_t)grow * Nc + bn + cc;
            float4 xv = *(const float4*)&X[gidx];
            vv.x += xv.x; vv.y += xv.y; vv.z += xv.z; vv.w += xv.w;
            *(float4*)&((float*)Cout)[gidx] = vv;
        } else { // EPI_SWIGLU
            float s0 = vv.x / (1.0f + expf(-vv.x)) * vv.y;
            float s1 = vv.z / (1.0f + expf(-vv.z)) * vv.w;
            int jo = (bn + cc) >> 1;
            *(__half2*)&((__half*)Cout)[(size_t)grow * (Nc >> 1) + jo] =
                __floats2half2_rn(s0, s1);
        }
    }
}

// ---------------- gather + rmsnorm ----------------
__global__ __launch_bounds__(128) void gather_rmsnorm_kernel(
    const int* __restrict__ ids, const float* __restrict__ emb,
    const float* __restrict__ xin, const float* __restrict__ g,
    float* __restrict__ xout, __half* __restrict__ h)
{
    int token = blockIdx.x;
    const float* src = ids ? (emb + (size_t)ids[token] * DMODEL)
                           : (xin + (size_t)token * DMODEL);
    int c = threadIdx.x * 4;
    float4 v = *(const float4*)&src[c];
    float ss = v.x * v.x + v.y * v.y + v.z * v.z + v.w * v.w;
#pragma unroll
    for (int off = 16; off > 0; off >>= 1) ss += __shfl_xor_sync(0xffffffffu, ss, off);
    __shared__ float sred[4];
    int warp = threadIdx.x >> 5, lane = threadIdx.x & 31;
    if (lane == 0) sred[warp] = ss;
    __syncthreads();
    float tot = sred[0] + sred[1] + sred[2] + sred[3];
    float scale = rsqrtf(tot * (1.0f / DMODEL) + EPSV);
    float4 gv = *(const float4*)&g[c];
    float4 o;
    o.x = v.x * scale * gv.x; o.y = v.y * scale * gv.y;
    o.z = v.z * scale * gv.z; o.w = v.w * scale * gv.w;
    if (xout) *(float4*)&xout[(size_t)token * DMODEL + c] = v;
    *(half4*)&h[(size_t)token * DMODEL + c] = f4_to_h4(o);
}

// ---------------- kv state partials (16-token tiles) ----------------
__global__ __launch_bounds__(256) void kv_partial_kernel(
    const __half* __restrict__ pk, const __half* __restrict__ v, float* __restrict__ kvp)
{
    int pair = blockIdx.x, chunk = blockIdx.y;
    int b = pair >> 1, kh = pair & 1;
    int tid = threadIdx.x;
    int ti = tid >> 4, tj = tid & 15;
    float acc[4][4], zacc[4];
#pragma unroll
    for (int a = 0; a < 4; a++) { zacc[a] = 0.f;
#pragma unroll
        for (int bb = 0; bb < 4; bb++) acc[a][bb] = 0.f; }
    __shared__ float spk[16][64], sv[16][64];
    int s0 = chunk * 1024;
    for (int sb = 0; sb < 1024; sb += 16) {
#pragma unroll
        for (int j = 0; j < 4; j++) {
            int idx = tid + j * 256;
            int t = idx >> 6, lane = idx & 63;
            int token = b * SEQ + s0 + sb + t;
            size_t base = ((size_t)token * NKV + kh) * 64 + lane;
            spk[t][lane] = __half2float(pk[base]);
            sv[t][lane]  = __half2float(v[base]);
        }
        __syncthreads();
#pragma unroll
        for (int t = 0; t < 16; t++) {
            float pm[4], vd[4];
#pragma unroll
            for (int mm = 0; mm < 4; mm++) pm[mm] = spk[t][ti * 4 + mm];
#pragma unroll
            for (int dd = 0; dd < 4; dd++) vd[dd] = sv[t][tj * 4 + dd];
#pragma unroll
            for (int mm = 0; mm < 4; mm++) {
#pragma unroll
                for (int dd = 0; dd < 4; dd++) acc[mm][dd] = fmaf(pm[mm], vd[dd], acc[mm][dd]);
                if (tj == 0) zacc[mm] += pm[mm];
            }
        }
        __syncthreads();
    }
    int pc = pair * 8 + chunk;
#pragma unroll
    for (int mm = 0; mm < 4; mm++) {
#pragma unroll
        for (int dd = 0; dd < 4; dd++)
            kvp[(size_t)pc * 4160 + (ti * 4 + mm) * 65 + tj * 4 + dd] = acc[mm][dd];
        if (tj == 0) kvp[(size_t)pc * 4160 + (ti * 4 + mm) * 65 + 64] = zacc[mm];
    }
}

// ---------------- num/den with fused chunk reduction ----------------
__global__ __launch_bounds__(256) void numden_kernel(
    const __half* __restrict__ pq, const float* __restrict__ kvp, __half* __restrict__ att)
{
    int b = blockIdx.y;
    __shared__ float skv[2 * 64 * 65];
    __shared__ float spq[4][64];
    for (int idx = threadIdx.x; idx < 8320; idx += 256) {
        int kh = idx / 4160, off = idx % 4160;
        const float* src = kvp + (size_t)((b * 2 + kh) * 8) * 4160 + off;
        float s = 0.f;
#pragma unroll
        for (int c = 0; c < 8; c++) s += src[c * 4160];
        skv[idx] = s;
    }
    __syncthreads();
    int group = threadIdx.x >> 6, lane = threadIdx.x & 63;
    int base = blockIdx.x * 128;
    for (int it = 0; it < 32; it++) {
        int th = base + it * 4 + group;
        size_t row = ((size_t)b * (SEQ * NHEAD) + th) * 64;
        spq[group][lane] = __half2float(pq[row + lane]);
        __syncthreads();
        int h = th & 7;
        const float* kvh = &skv[(h >> 2) * 4160];
        float num = 0.f, den = 0.f;
#pragma unroll
        for (int m = 0; m < 64; m++) {
            float p = spq[group][m];
            num = fmaf(p, kvh[m * 65 + lane], num);
            den = fmaf(p, kvh[m * 65 + 64], den);
        }
        att[row + lane] = __float2half(num / (den + EPSV));
        __syncthreads();
    }
}

// ---------------- pool + head ----------------
__global__ __launch_bounds__(256) void pool_kernel(
    const float* __restrict__ x, float* __restrict__ xm)
{
    int b = blockIdx.y;
    int c = blockIdx.x * 64 + (threadIdx.x & 63);
    int part = threadIdx.x >> 6;
    float s = 0.f;
    for (int t = part; t < SEQ; t += 4)
        s += x[((size_t)b * SEQ + t) * DMODEL + c];
    __shared__ float red[4][64];
    red[part][threadIdx.x & 63] = s;
    __syncthreads();
    if (part == 0) {
        int l = threadIdx.x & 63;
        xm[b * DMODEL + c] = red[0][l] + red[1][l] + red[2][l] + red[3][l];
    }
}

__global__ __launch_bounds__(512) void head_kernel(
    const float* __restrict__ xm, const float* __restrict__ Wc,
    const float* __restrict__ bc, float* __restrict__ out)
{
    int warp = threadIdx.x >> 5, lane = threadIdx.x & 31;
    int b = warp >> 1, cls = warp & 1;
    float s = 0.f;
    for (int d = lane; d < DMODEL; d += 32)
        s += xm[b * DMODEL + d] * Wc[d * NCLS + cls];
#pragma unroll
    for (int off = 16; off > 0; off >>= 1) s += __shfl_xor_sync(0xffffffffu, s, off);
    if (lane == 0) out[b * NCLS + cls] = s * (1.0f / SEQ) + bc[cls];
}

// ---------------- launch ----------------
#define STG128B ((128 * 40 + 32 * 136) * 2)           // bytes per stage, BN=128
#define STG64B  ((128 * 40 + 32 * 72) * 2)
#define CS128B  (128 * 132 * 4)                       // 67584
#define CS64B   (128 * 68 * 4)                        // 34816
#define SMEM_BN128_V ((STAGES * STG128B) > CS128B ? (STAGES * STG128B) : CS128B)  // 75776
#define SMEM_BN64_V  ((STAGES * STG64B) > CS64B ? (STAGES * STG64B) : CS64B)      // 59392

extern "C" void kernel_launch(void* const* d_in, const int* in_sizes, int n_in,
                              void* d_out, int out_size)
{
    (void)in_sizes; (void)n_in; (void)out_size;
    const int*   ids  = (const int*)  d_in[0];
    const float* emb  = (const float*)d_in[1];
    const float* Wq   = (const float*)d_in[2];
    const float* Wk   = (const float*)d_in[3];
    const float* Wv   = (const float*)d_in[4];
    const float* Wphi = (const float*)d_in[5];
    const float* Wo   = (const float*)d_in[6];
    const float* g1   = (const float*)d_in[7];
    const float* g2   = (const float*)d_in[8];
    const float* Wg   = (const float*)d_in[9];
    const float* Wu   = (const float*)d_in[10];
    const float* Wd   = (const float*)d_in[11];
    const float* Wc   = (const float*)d_in[12];
    const float* bc   = (const float*)d_in[13];
    float* out = (float*)d_out;

    float *x, *kvp, *xm;
    __half *h, *qkv, *pqk, *att, *gu;
    __half *WqkvH, *WphiH, *WoH, *WguH, *WdH;
    cudaGetSymbolAddress((void**)&x,    g_x);
    cudaGetSymbolAddress((void**)&h,    g_h);
    cudaGetSymbolAddress((void**)&qkv,  g_qkv);
    cudaGetSymbolAddress((void**)&pqk,  g_pqk);
    cudaGetSymbolAddress((void**)&att,  g_att);
    cudaGetSymbolAddress((void**)&gu,   g_gu);
    cudaGetSymbolAddress((void**)&kvp,  g_kvp);
    cudaGetSymbolAddress((void**)&xm,   g_xm);
    cudaGetSymbolAddress((void**)&WqkvH, g_WqkvH);
    cudaGetSymbolAddress((void**)&WphiH, g_WphiH);
    cudaGetSymbolAddress((void**)&WoH,   g_WoH);
    cudaGetSymbolAddress((void**)&WguH,  g_WguH);
    cudaGetSymbolAddress((void**)&WdH,   g_WdH);

    cudaFuncSetAttribute(gemm_h<128, EPI_QKV>,    cudaFuncAttributeMaxDynamicSharedMemorySize, SMEM_BN128_V);
    cudaFuncSetAttribute(gemm_h<128, EPI_RES>,    cudaFuncAttributeMaxDynamicSharedMemorySize, SMEM_BN128_V);
    cudaFuncSetAttribute(gemm_h<128, EPI_SWIGLU>, cudaFuncAttributeMaxDynamicSharedMemorySize, SMEM_BN128_V);
    cudaFuncSetAttribute(gemm_h<64,  EPI_EXPABS>, cudaFuncAttributeMaxDynamicSharedMemorySize, SMEM_BN64_V);

    // 1. merged weight conversion
    conv_all<<<(CTOT + 255) / 256, 256>>>(Wq, Wk, Wv, Wg, Wu, Wphi, Wo, Wd,
                                          WqkvH, WguH, WphiH, WoH, WdH);

    // 2. embedding gather + rmsnorm
    gather_rmsnorm_kernel<<<NTOK, 128>>>(ids, emb, nullptr, g1, x, h);

    // 3. fused qkv projection
    {
        dim3 grid(768 / 128, NTOK / 128);
        gemm_h<128, EPI_QKV><<<grid, NTHR, SMEM_BN128_V>>>(h, WqkvH, qkv, nullptr, NTOK, DMODEL, 768);
    }

    // 4. single Laplacian feature-map GEMM over q-rows + k-rows
    {
        dim3 grid(1, NTOK * (NHEAD + NKV) / 128);
        gemm_h<64, EPI_EXPABS><<<grid, NTHR, SMEM_BN64_V>>>(
            qkv, WphiH, pqk, nullptr, NTOK * (NHEAD + NKV), DHEAD, MFEAT);
    }

    // 5. global kv state partials
    {
        dim3 gp(BATCH * NKV, 8);
        kv_partial_kernel<<<gp, 256>>>(pqk + (size_t)NTOK * NHEAD * MFEAT,
                                       qkv + (size_t)NTOK * 640, kvp);
    }

    // 6. num/den -> attn
    {
        dim3 gn(SEQ * NHEAD / 128, BATCH);
        numden_kernel<<<gn, 256>>>(pqk, kvp, att);
    }

    // 7. output projection + residual
    {
        dim3 grid(DMODEL / 128, NTOK / 128);
        gemm_h<128, EPI_RES><<<grid, NTHR, SMEM_BN128_V>>>(att, WoH, x, x, NTOK, DMODEL, DMODEL);
    }

    // 8. pre-FFN rmsnorm
    gather_rmsnorm_kernel<<<NTOK, 128>>>(nullptr, nullptr, x, g2, nullptr, h);

    // 9. fused SwiGLU up
    {
        dim3 grid(4096 / 128, NTOK / 128);
        gemm_h<128, EPI_SWIGLU><<<grid, NTHR, SMEM_BN128_V>>>(h, WguH, gu, nullptr, NTOK, DMODEL, 4096);
    }
    // 10. down proj + residual
    {
        dim3 grid(DMODEL / 128, NTOK / 128);
        gemm_h<128, EPI_RES><<<grid, NTHR, SMEM_BN128_V>>>(gu, WdH, x, x, NTOK, DFF, DMODEL);
    }

    // 11. mean pool + head
    {
        dim3 gpool(DMODEL / 64, BATCH);
        pool_kernel<<<gpool, 256>>>(x, xm);
    }
    head_kernel<<<1, 512>>>(xm, Wc, bc, out);
}

// round 9
// speedup vs baseline: 1.0287x; 1.0260x over previous
#include <cuda_runtime.h>
#include <cuda_fp16.h>
#include <cuda_pipeline.h>
#include <mma.h>
#include <math.h>
#include <cstdint>

using namespace nvcuda;

// ---------------- problem constants ----------------
#define NTOK   65536
#define BATCH  8
#define SEQ    8192
#define DMODEL 512
#define NHEAD  8
#define NKV    2
#define DHEAD  64
#define MFEAT  64
#define DFF    2048
#define NCLS   2
#define EPSV   1e-6f

// ---------------- scratch ----------------
__device__ float  g_x   [NTOK * DMODEL];
__device__ __half g_h   [NTOK * DMODEL];
__device__ __half g_qkv [NTOK * (DMODEL + 2*128)];   // q | k | v contiguous blocks
__device__ __half g_pqk [NTOK * (NHEAD + NKV) * MFEAT];  // pq rows then pk rows
__device__ __half g_att [NTOK * DMODEL];
__device__ __half g_gu  [NTOK * DFF];
__device__ float  g_kvp [128 * 64 * 65];
__device__ float  g_xm  [BATCH * DMODEL];
// converted fp16 weights, row-major [K, N]
__device__ __half g_WqkvH[DMODEL * 768];
__device__ __half g_WphiH[DHEAD * MFEAT];
__device__ __half g_WoH  [DMODEL * DMODEL];
__device__ __half g_WguH [DMODEL * (2*DFF)];   // interleaved g,u columns
__device__ __half g_WdH  [DFF * DMODEL];

struct alignas(8) half4 { __half2 a, b; };
__device__ __forceinline__ half4 f4_to_h4(float4 v) {
    half4 r; r.a = __floats2half2_rn(v.x, v.y); r.b = __floats2half2_rn(v.z, v.w); return r;
}

// ---------------- single merged weight conversion ----------------
#define CQKV 393216
#define CGU  2097152
#define CPHI 4096
#define CWO  262144
#define CWD  1048576
#define CTOT (CQKV + CGU + CPHI + CWO + CWD)

__global__ void conv_all(const float* __restrict__ Wq, const float* __restrict__ Wk,
                         const float* __restrict__ Wv, const float* __restrict__ Wg,
                         const float* __restrict__ Wu, const float* __restrict__ Wphi,
                         const float* __restrict__ Wo, const float* __restrict__ Wd,
                         __half* __restrict__ WqkvH, __half* __restrict__ WguH,
                         __half* __restrict__ WphiH, __half* __restrict__ WoH,
                         __half* __restrict__ WdH)
{
    int idx = blockIdx.x * 256 + threadIdx.x;
    if (idx < CQKV) {
        int r = idx / 768, c = idx % 768;
        float v = (c < 512) ? Wq[r * 512 + c]
                            : (c < 640 ? Wk[r * 128 + c - 512] : Wv[r * 128 + c - 640]);
        WqkvH[idx] = __float2half(v);
        return;
    }
    idx -= CQKV;
    if (idx < CGU) {
        int r = idx >> 12, c = idx & 4095;
        int j = c >> 1;
        float v = (c & 1) ? Wu[r * DFF + j] : Wg[r * DFF + j];
        WguH[idx] = __float2half(v);
        return;
    }
    idx -= CGU;
    if (idx < CPHI) { WphiH[idx] = __float2half(Wphi[idx]); return; }
    idx -= CPHI;
    if (idx < CWO)  { WoH[idx]   = __float2half(Wo[idx]);   return; }
    idx -= CWO;
    if (idx < CWD)  { WdH[idx]   = __float2half(Wd[idx]);   return; }
}

// ---------------- fp16 WMMA GEMM: 128 threads, 64x64 warp tile, 3 blocks/SM ----------------
#define EPI_QKV    0
#define EPI_EXPABS 1
#define EPI_RES    2
#define EPI_SWIGLU 3
#define STAGES 4
#define NTHR   128

template<int BN, int EPI>
__global__ __launch_bounds__(NTHR, 3) void gemm_h(
    const __half* __restrict__ A, const __half* __restrict__ B,
    void* __restrict__ Cout, const float* __restrict__ X,
    int M, int K, int Nc)
{
    constexpr int BM = 128, BK = 32;
    constexpr int LDA_S = BK + 8;
    constexpr int LDB_S = BN + 8;
    constexpr int LDC_S = BN + 4;
    constexpr int MI = 4;               // 64/16 m-frags per warp
    constexpr int NJ = BN / 32;         // warp n-tile = BN/2
    constexpr int A_ELE = BM * LDA_S;
    constexpr int B_ELE = BK * LDB_S;
    constexpr int STG_ELE = A_ELE + B_ELE;

    extern __shared__ __align__(16) char smem_raw[];
    __half* stg = (__half*)smem_raw;

    const int tid  = threadIdx.x;
    const int bm   = blockIdx.y * BM;
    const int bn   = blockIdx.x * BN;
    const int warp = tid >> 5;
    const int wm   = (warp & 1) * 64;
    const int wn   = (warp >> 1) * (BN / 2);

    wmma::fragment<wmma::accumulator, 16, 16, 16, float> c[MI][NJ];
#pragma unroll
    for (int i = 0; i < MI; i++)
#pragma unroll
        for (int j = 0; j < NJ; j++) wmma::fill_fragment(c[i][j], 0.0f);

    const int nK = K / BK;

    auto load_stage = [&](int kt, int s) {
        __half* As = stg + s * STG_ELE;
        __half* Bs = As + A_ELE;
#pragma unroll
        for (int i = 0; i < 4; i++) {
            int idx = tid + i * NTHR;
            int r  = idx >> 2;
            int cc = (idx & 3) * 8;
            __pipeline_memcpy_async(&As[r * LDA_S + cc],
                                    &A[(size_t)(bm + r) * K + kt + cc], 16);
        }
        constexpr int CH = BN / 8;
        constexpr int NB = (BK * CH) / NTHR;
#pragma unroll
        for (int i = 0; i < NB; i++) {
            int idx = tid + i * NTHR;
            int r  = idx / CH;
            int cc = (idx % CH) * 8;
            __pipeline_memcpy_async(&Bs[r * LDB_S + cc],
                                    &B[(size_t)(kt + r) * Nc + bn + cc], 16);
        }
    };

#pragma unroll
    for (int s = 0; s < STAGES - 1; s++) {
        if (s < nK) load_stage(s * BK, s);
        __pipeline_commit();
    }

    for (int kt_i = 0; kt_i < nK; kt_i++) {
        __pipeline_wait_prior(STAGES - 2);
        __syncthreads();
        int ldk = kt_i + STAGES - 1;
        if (ldk < nK) load_stage(ldk * BK, ldk % STAGES);
        __pipeline_commit();

        int s = kt_i % STAGES;
        __half* As = stg + s * STG_ELE;
        __half* Bs = As + A_ELE;
#pragma unroll
        for (int kk = 0; kk < BK; kk += 16) {
            wmma::fragment<wmma::matrix_a, 16, 16, 16, __half, wmma::row_major> a[MI];
            wmma::fragment<wmma::matrix_b, 16, 16, 16, __half, wmma::row_major> b[NJ];
#pragma unroll
            for (int i = 0; i < MI; i++)
                wmma::load_matrix_sync(a[i], &As[(wm + i * 16) * LDA_S + kk], LDA_S);
#pragma unroll
            for (int j = 0; j < NJ; j++)
                wmma::load_matrix_sync(b[j], &Bs[kk * LDB_S + wn + j * 16], LDB_S);
#pragma unroll
            for (int i = 0; i < MI; i++)
#pragma unroll
                for (int j = 0; j < NJ; j++)
                    wmma::mma_sync(c[i][j], a[i], b[j], c[i][j]);
        }
    }

    // ---- epilogue ----
    if (EPI == EPI_SWIGLU) {
        // position-dependent (g,u) pairing: stage through smem, two 64-row passes
        __syncthreads();
        float* Cs = (float*)smem_raw;              // 64 * LDC_S floats = 33792 B
        constexpr int F4R = BN / 4;
        constexpr int NIT = (64 * F4R) / NTHR;
#pragma unroll
        for (int hrow = 0; hrow < 2; hrow++) {
            __syncthreads();
            if ((wm >> 6) == hrow) {
#pragma unroll
                for (int i = 0; i < MI; i++)
#pragma unroll
                    for (int j = 0; j < NJ; j++)
                        wmma::store_matrix_sync(&Cs[((wm & 63) + i * 16) * LDC_S + wn + j * 16],
                                                c[i][j], LDC_S, wmma::mem_row_major);
            }
            __syncthreads();
#pragma unroll
            for (int i = 0; i < NIT; i++) {
                int e  = tid + i * NTHR;
                int r  = e / F4R;
                int cc = (e % F4R) * 4;
                float4 vv = *(float4*)&Cs[r * LDC_S + cc];
                int grow = bm + hrow * 64 + r;
                float s0 = vv.x / (1.0f + expf(-vv.x)) * vv.y;
                float s1 = vv.z / (1.0f + expf(-vv.z)) * vv.w;
                int jo = (bn + cc) >> 1;
                *(__half2*)&((__half*)Cout)[(size_t)grow * (Nc >> 1) + jo] =
                    __floats2half2_rn(s0, s1);
            }
        }
    } else {
        // fragment-direct epilogues (no smem, no syncs)
#pragma unroll
        for (int i = 0; i < MI; i++) {
#pragma unroll
            for (int j = 0; j < NJ; j++) {
                int grow = bm + wm + i * 16;
                int gcol = bn + wn + j * 16;
                if (EPI == EPI_RES) {
                    wmma::fragment<wmma::accumulator, 16, 16, 16, float> xf;
                    float* o = (float*)Cout + (size_t)grow * Nc + gcol;
                    wmma::load_matrix_sync(xf, X + (size_t)grow * Nc + gcol, Nc,
                                           wmma::mem_row_major);
#pragma unroll
                    for (int t = 0; t < xf.num_elements; t++)
                        xf.x[t] += c[i][j].x[t];
                    wmma::store_matrix_sync(o, xf, Nc, wmma::mem_row_major);
                } else {
                    wmma::fragment<wmma::accumulator, 16, 16, 16, __half> ch;
#pragma unroll
                    for (int t = 0; t < ch.num_elements; t++) {
                        float v = c[i][j].x[t];
                        if (EPI == EPI_EXPABS) v = expf(-fabsf(v));
                        ch.x[t] = __float2half(v);
                    }
                    __half* dst; int ld, c0;
                    if (EPI == EPI_QKV) {
                        if (gcol < 512)      { dst = (__half*)Cout;                    ld = 512; c0 = gcol; }
                        else if (gcol < 640) { dst = (__half*)Cout + (size_t)M * 512;  ld = 128; c0 = gcol - 512; }
                        else                 { dst = (__half*)Cout + (size_t)M * 640;  ld = 128; c0 = gcol - 640; }
                    } else {
                        dst = (__half*)Cout; ld = Nc; c0 = gcol;
                    }
                    wmma::store_matrix_sync(dst + (size_t)grow * ld + c0, ch, ld,
                                            wmma::mem_row_major);
                }
            }
        }
    }
}

// ---------------- gather + rmsnorm ----------------
__global__ __launch_bounds__(128) void gather_rmsnorm_kernel(
    const int* __restrict__ ids, const float* __restrict__ emb,
    const float* __restrict__ xin, const float* __restrict__ g,
    float* __restrict__ xout, __half* __restrict__ h)
{
    int token = blockIdx.x;
    const float* src = ids ? (emb + (size_t)ids[token] * DMODEL)
                           : (xin + (size_t)token * DMODEL);
    int c = threadIdx.x * 4;
    float4 v = *(const float4*)&src[c];
    float ss = v.x * v.x + v.y * v.y + v.z * v.z + v.w * v.w;
#pragma unroll
    for (int off = 16; off > 0; off >>= 1) ss += __shfl_xor_sync(0xffffffffu, ss, off);
    __shared__ float sred[4];
    int warp = threadIdx.x >> 5, lane = threadIdx.x & 31;
    if (lane == 0) sred[warp] = ss;
    __syncthreads();
    float tot = sred[0] + sred[1] + sred[2] + sred[3];
    float scale = rsqrtf(tot * (1.0f / DMODEL) + EPSV);
    float4 gv = *(const float4*)&g[c];
    float4 o;
    o.x = v.x * scale * gv.x; o.y = v.y * scale * gv.y;
    o.z = v.z * scale * gv.z; o.w = v.w * scale * gv.w;
    if (xout) *(float4*)&xout[(size_t)token * DMODEL + c] = v;
    *(half4*)&h[(size_t)token * DMODEL + c] = f4_to_h4(o);
}

// ---------------- kv state partials (16-token tiles) ----------------
__global__ __launch_bounds__(256) void kv_partial_kernel(
    const __half* __restrict__ pk, const __half* __restrict__ v, float* __restrict__ kvp)
{
    int pair = blockIdx.x, chunk = blockIdx.y;
    int b = pair >> 1, kh = pair & 1;
    int tid = threadIdx.x;
    int ti = tid >> 4, tj = tid & 15;
    float acc[4][4], zacc[4];
#pragma unroll
    for (int a = 0; a < 4; a++) { zacc[a] = 0.f;
#pragma unroll
        for (int bb = 0; bb < 4; bb++) acc[a][bb] = 0.f; }
    __shared__ float spk[16][64], sv[16][64];
    int s0 = chunk * 1024;
    for (int sb = 0; sb < 1024; sb += 16) {
#pragma unroll
        for (int j = 0; j < 4; j++) {
            int idx = tid + j * 256;
            int t = idx >> 6, lane = idx & 63;
            int token = b * SEQ + s0 + sb + t;
            size_t base = ((size_t)token * NKV + kh) * 64 + lane;
            spk[t][lane] = __half2float(pk[base]);
            sv[t][lane]  = __half2float(v[base]);
        }
        __syncthreads();
#pragma unroll
        for (int t = 0; t < 16; t++) {
            float pm[4], vd[4];
#pragma unroll
            for (int mm = 0; mm < 4; mm++) pm[mm] = spk[t][ti * 4 + mm];
#pragma unroll
            for (int dd = 0; dd < 4; dd++) vd[dd] = sv[t][tj * 4 + dd];
#pragma unroll
            for (int mm = 0; mm < 4; mm++) {
#pragma unroll
                for (int dd = 0; dd < 4; dd++) acc[mm][dd] = fmaf(pm[mm], vd[dd], acc[mm][dd]);
                if (tj == 0) zacc[mm] += pm[mm];
            }
        }
        __syncthreads();
    }
    int pc = pair * 8 + chunk;
#pragma unroll
    for (int mm = 0; mm < 4; mm++) {
#pragma unroll
        for (int dd = 0; dd < 4; dd++)
            kvp[(size_t)pc * 4160 + (ti * 4 + mm) * 65 + tj * 4 + dd] = acc[mm][dd];
        if (tj == 0) kvp[(size_t)pc * 4160 + (ti * 4 + mm) * 65 + 64] = zacc[mm];
    }
}

// ---------------- num/den with fused chunk reduction ----------------
__global__ __launch_bounds__(256) void numden_kernel(
    const __half* __restrict__ pq, const float* __restrict__ kvp, __half* __restrict__ att)
{
    int b = blockIdx.y;
    __shared__ float skv[2 * 64 * 65];
    __shared__ float spq[4][64];
    for (int idx = threadIdx.x; idx < 8320; idx += 256) {
        int kh = idx / 4160, off = idx % 4160;
        const float* src = kvp + (size_t)((b * 2 + kh) * 8) * 4160 + off;
        float s = 0.f;
#pragma unroll
        for (int c = 0; c < 8; c++) s += src[c * 4160];
        skv[idx] = s;
    }
    __syncthreads();
    int group = threadIdx.x >> 6, lane = threadIdx.x & 63;
    int base = blockIdx.x * 128;
    for (int it = 0; it < 32; it++) {
        int th = base + it * 4 + group;
        size_t row = ((size_t)b * (SEQ * NHEAD) + th) * 64;
        spq[group][lane] = __half2float(pq[row + lane]);
        __syncthreads();
        int h = th & 7;
        const float* kvh = &skv[(h >> 2) * 4160];
        float num = 0.f, den = 0.f;
#pragma unroll
        for (int m = 0; m < 64; m++) {
            float p = spq[group][m];
            num = fmaf(p, kvh[m * 65 + lane], num);
            den = fmaf(p, kvh[m * 65 + 64], den);
        }
        att[row + lane] = __float2half(num / (den + EPSV));
        __syncthreads();
    }
}

// ---------------- pool + head ----------------
__global__ __launch_bounds__(256) void pool_kernel(
    const float* __restrict__ x, float* __restrict__ xm)
{
    int b = blockIdx.y;
    int c = blockIdx.x * 64 + (threadIdx.x & 63);
    int part = threadIdx.x >> 6;
    float s = 0.f;
    for (int t = part; t < SEQ; t += 4)
        s += x[((size_t)b * SEQ + t) * DMODEL + c];
    __shared__ float red[4][64];
    red[part][threadIdx.x & 63] = s;
    __syncthreads();
    if (part == 0) {
        int l = threadIdx.x & 63;
        xm[b * DMODEL + c] = red[0][l] + red[1][l] + red[2][l] + red[3][l];
    }
}

__global__ __launch_bounds__(512) void head_kernel(
    const float* __restrict__ xm, const float* __restrict__ Wc,
    const float* __restrict__ bc, float* __restrict__ out)
{
    int warp = threadIdx.x >> 5, lane = threadIdx.x & 31;
    int b = warp >> 1, cls = warp & 1;
    float s = 0.f;
    for (int d = lane; d < DMODEL; d += 32)
        s += xm[b * DMODEL + d] * Wc[d * NCLS + cls];
#pragma unroll
    for (int off = 16; off > 0; off >>= 1) s += __shfl_xor_sync(0xffffffffu, s, off);
    if (lane == 0) out[b * NCLS + cls] = s * (1.0f / SEQ) + bc[cls];
}

// ---------------- launch ----------------
#define SMEM_BN128_V ((STAGES * (128 * 40 + 32 * 136)) * 2)   // 75776
#define SMEM_BN64_V  ((STAGES * (128 * 40 + 32 * 72)) * 2)    // 59392

extern "C" void kernel_launch(void* const* d_in, const int* in_sizes, int n_in,
                              void* d_out, int out_size)
{
    (void)in_sizes; (void)n_in; (void)out_size;
    const int*   ids  = (const int*)  d_in[0];
    const float* emb  = (const float*)d_in[1];
    const float* Wq   = (const float*)d_in[2];
    const float* Wk   = (const float*)d_in[3];
    const float* Wv   = (const float*)d_in[4];
    const float* Wphi = (const float*)d_in[5];
    const float* Wo   = (const float*)d_in[6];
    const float* g1   = (const float*)d_in[7];
    const float* g2   = (const float*)d_in[8];
    const float* Wg   = (const float*)d_in[9];
    const float* Wu   = (const float*)d_in[10];
    const float* Wd   = (const float*)d_in[11];
    const float* Wc   = (const float*)d_in[12];
    const float* bc   = (const float*)d_in[13];
    float* out = (float*)d_out;

    float *x, *kvp, *xm;
    __half *h, *qkv, *pqk, *att, *gu;
    __half *WqkvH, *WphiH, *WoH, *WguH, *WdH;
    cudaGetSymbolAddress((void**)&x,    g_x);
    cudaGetSymbolAddress((void**)&h,    g_h);
    cudaGetSymbolAddress((void**)&qkv,  g_qkv);
    cudaGetSymbolAddress((void**)&pqk,  g_pqk);
    cudaGetSymbolAddress((void**)&att,  g_att);
    cudaGetSymbolAddress((void**)&gu,   g_gu);
    cudaGetSymbolAddress((void**)&kvp,  g_kvp);
    cudaGetSymbolAddress((void**)&xm,   g_xm);
    cudaGetSymbolAddress((void**)&WqkvH, g_WqkvH);
    cudaGetSymbolAddress((void**)&WphiH, g_WphiH);
    cudaGetSymbolAddress((void**)&WoH,   g_WoH);
    cudaGetSymbolAddress((void**)&WguH,  g_WguH);
    cudaGetSymbolAddress((void**)&WdH,   g_WdH);

    cudaFuncSetAttribute(gemm_h<128, EPI_QKV>,    cudaFuncAttributeMaxDynamicSharedMemorySize, SMEM_BN128_V);
    cudaFuncSetAttribute(gemm_h<128, EPI_RES>,    cudaFuncAttributeMaxDynamicSharedMemorySize, SMEM_BN128_V);
    cudaFuncSetAttribute(gemm_h<128, EPI_SWIGLU>, cudaFuncAttributeMaxDynamicSharedMemorySize, SMEM_BN128_V);
    cudaFuncSetAttribute(gemm_h<64,  EPI_EXPABS>, cudaFuncAttributeMaxDynamicSharedMemorySize, SMEM_BN64_V);

    // 1. merged weight conversion
    conv_all<<<(CTOT + 255) / 256, 256>>>(Wq, Wk, Wv, Wg, Wu, Wphi, Wo, Wd,
                                          WqkvH, WguH, WphiH, WoH, WdH);

    // 2. embedding gather + rmsnorm
    gather_rmsnorm_kernel<<<NTOK, 128>>>(ids, emb, nullptr, g1, x, h);

    // 3. fused qkv projection
    {
        dim3 grid(768 / 128, NTOK / 128);
        gemm_h<128, EPI_QKV><<<grid, NTHR, SMEM_BN128_V>>>(h, WqkvH, qkv, nullptr, NTOK, DMODEL, 768);
    }

    // 4. single Laplacian feature-map GEMM over q-rows + k-rows
    {
        dim3 grid(1, NTOK * (NHEAD + NKV) / 128);
        gemm_h<64, EPI_EXPABS><<<grid, NTHR, SMEM_BN64_V>>>(
            qkv, WphiH, pqk, nullptr, NTOK * (NHEAD + NKV), DHEAD, MFEAT);
    }

    // 5. global kv state partials
    {
        dim3 gp(BATCH * NKV, 8);
        kv_partial_kernel<<<gp, 256>>>(pqk + (size_t)NTOK * NHEAD * MFEAT,
                                       qkv + (size_t)NTOK * 640, kvp);
    }

    // 6. num/den -> attn
    {
        dim3 gn(SEQ * NHEAD / 128, BATCH);
        numden_kernel<<<gn, 256>>>(pqk, kvp, att);
    }

    // 7. output projection + residual
    {
        dim3 grid(DMODEL / 128, NTOK / 128);
        gemm_h<128, EPI_RES><<<grid, NTHR, SMEM_BN128_V>>>(att, WoH, x, x, NTOK, DMODEL, DMODEL);
    }

    // 8. pre-FFN rmsnorm
    gather_rmsnorm_kernel<<<NTOK, 128>>>(nullptr, nullptr, x, g2, nullptr, h);

    // 9. fused SwiGLU up
    {
        dim3 grid(4096 / 128, NTOK / 128);
        gemm_h<128, EPI_SWIGLU><<<grid, NTHR, SMEM_BN128_V>>>(h, WguH, gu, nullptr, NTOK, DMODEL, 4096);
    }
    // 10. down proj + residual
    {
        dim3 grid(DMODEL / 128, NTOK / 128);
        gemm_h<128, EPI_RES><<<grid, NTHR, SMEM_BN128_V>>>(gu, WdH, x, x, NTOK, DFF, DMODEL);
    }

    // 11. mean pool + head
    {
        dim3 gpool(DMODEL / 64, BATCH);
        pool_kernel<<<gpool, 256>>>(x, xm);
    }
    head_kernel<<<1, 512>>>(xm, Wc, bc, out);
}